// round 15
// baseline (speedup 1.0000x reference)
#include <cuda_runtime.h>
#include <cuda_fp16.h>
#include <math.h>

#define N_NODES   100000
#define C_DIM     64
#define C2        32          // half2 pairs per row
#define E_EDGES   3200000
#define NUM_LAYERS 10
#define ALPHA     0.9f
#define ONE_M_ALPHA 0.1f
#define SCAN_TILE 1024
#define NBLK_SCAN ((N_NODES + SCAN_TILE - 1) / SCAN_TILE)   // 98

// ---- static device scratch (no allocation allowed) ----
__device__ int     g_deg[N_NODES];
__device__ int     g_rowptr[N_NODES + 1];
__device__ int     g_cursor[N_NODES];
__device__ int     g_col[E_EDGES];
__device__ int     g_part[NBLK_SCAN];
__device__ float   g_norm[N_NODES];
__device__ float   g_last[N_NODES * C_DIM];
__device__ __half2 g_zA[N_NODES * C2];
__device__ __half2 g_zB[N_NODES * C2];
__device__ int     g_mask_is_byte;

// ------------------------------------------------------------------
__global__ void detect_mask_kernel(const unsigned char* __restrict__ m) {
    __shared__ int any;
    int t = threadIdx.x;
    if (t == 0) any = 0;
    __syncthreads();
    for (int i = t; i < 1024; i += blockDim.x) {
        if ((i & 3) != 0 && m[i] != 0) atomicOr(&any, 1);
    }
    __syncthreads();
    if (t == 0) g_mask_is_byte = any;
}

__global__ void zero_deg_kernel(int n) {
    int i = blockIdx.x * blockDim.x + threadIdx.x;
    if (i < n) g_deg[i] = 0;
}

__global__ void count_deg_kernel(const int* __restrict__ dst, int e) {
    int i = blockIdx.x * blockDim.x + threadIdx.x;
    if (i < e) {
        int d = dst[i];
        if (d >= 0 && d < N_NODES) atomicAdd(&g_deg[d], 1);
    }
}

__global__ void __launch_bounds__(SCAN_TILE)
scan_pass1_kernel(int n) {
    __shared__ int sh[SCAN_TILE];
    int i = blockIdx.x * SCAN_TILE + threadIdx.x;
    sh[threadIdx.x] = (i < n) ? g_deg[i] : 0;
    __syncthreads();
    #pragma unroll
    for (int off = SCAN_TILE / 2; off > 0; off >>= 1) {
        if (threadIdx.x < off) sh[threadIdx.x] += sh[threadIdx.x + off];
        __syncthreads();
    }
    if (threadIdx.x == 0) g_part[blockIdx.x] = sh[0];
}

// block-local scan; each block also scans the 98 partials itself (replaces pass2)
__global__ void __launch_bounds__(SCAN_TILE)
scan_pass3_kernel(int n) {
    __shared__ int sh[SCAN_TILE];
    __shared__ int shp[128];
    __shared__ int blk_off;
    int t = threadIdx.x;

    if (t < 128) {
        shp[t] = (t < NBLK_SCAN) ? g_part[t] : 0;
    }
    __syncthreads();
    #pragma unroll
    for (int off = 1; off < 128; off <<= 1) {
        int add = 0;
        if (t < 128 && t >= off) add = shp[t - off];
        __syncthreads();
        if (t < 128) shp[t] += add;
        __syncthreads();
    }
    if (t == 0) {
        int b = blockIdx.x;
        int incl = shp[b];
        int own  = (b < NBLK_SCAN) ? g_part[b] : 0;
        blk_off = incl - own;                       // exclusive prefix
        if (b == 0) g_rowptr[n] = shp[127];         // total
    }
    __syncthreads();

    int i = blockIdx.x * SCAN_TILE + t;
    int v = (i < n) ? g_deg[i] : 0;
    sh[t] = v;
    __syncthreads();
    #pragma unroll
    for (int off = 1; off < SCAN_TILE; off <<= 1) {
        int add = (t >= off) ? sh[t - off] : 0;
        __syncthreads();
        sh[t] += add;
        __syncthreads();
    }
    if (i < n) {
        int excl = blk_off + sh[t] - v;
        g_rowptr[i] = excl;
        g_cursor[i] = excl;
        g_norm[i]   = rsqrtf((float)(v > 0 ? v : 1));
    }
}

__global__ void fill_csr_kernel(const int* __restrict__ src,
                                const int* __restrict__ dst, int e) {
    int i = blockIdx.x * blockDim.x + threadIdx.x;
    if (i < e) {
        int d = dst[i];
        int s = src[i];
        if (d >= 0 && d < N_NODES && s >= 0 && s < N_NODES) {
            int p = atomicAdd(&g_cursor[d], 1);
            g_col[p] = s;
        }
    }
}

__global__ void init_kernel(const float* __restrict__ labels,
                            const void* __restrict__ mask_raw, int n) {
    int idx = blockIdx.x * blockDim.x + threadIdx.x;   // over n*C2 pairs
    if (idx >= n * C2) return;
    int node = idx >> 5;
    float2 l = ((const float2*)labels)[idx];
    int mv = g_mask_is_byte ? (int)((const unsigned char*)mask_raw)[node]
                            : ((const int*)mask_raw)[node];
    float m  = mv ? 1.0f : 0.0f;
    float vx = l.x * m, vy = l.y * m;
    ((float2*)g_last)[idx] = make_float2(ONE_M_ALPHA * vx, ONE_M_ALPHA * vy);
    float nn = g_norm[node];
    g_zA[idx] = __floats2half2_rn(nn * vx, nn * vy);
}

// ------------------------------------------------------------------
// packed f32x2 accumulate (Blackwell): one instruction for 2 fp32 adds
__device__ __forceinline__ void add_f32x2(float2& acc, float2 v) {
    unsigned long long a = *(unsigned long long*)&acc;
    unsigned long long b = *(unsigned long long*)&v;
    asm("add.rn.f32x2 %0, %0, %1;" : "+l"(a) : "l"(b));
    *(unsigned long long*)&acc = a;
}

__device__ __forceinline__ void acc_chunk(float2* a, uint4 v) {
    add_f32x2(a[0], __half22float2(*(const __half2*)&v.x));
    add_f32x2(a[1], __half22float2(*(const __half2*)&v.y));
    add_f32x2(a[2], __half22float2(*(const __half2*)&v.z));
    add_f32x2(a[3], __half22float2(*(const __half2*)&v.w));
}

// pair two edges in fp16, then fp32 accumulate
__device__ __forceinline__ void acc_pair(float2* a, uint4 u, uint4 v) {
    __half2 p0 = __hadd2(*(const __half2*)&u.x, *(const __half2*)&v.x);
    __half2 p1 = __hadd2(*(const __half2*)&u.y, *(const __half2*)&v.y);
    __half2 p2 = __hadd2(*(const __half2*)&u.z, *(const __half2*)&v.z);
    __half2 p3 = __hadd2(*(const __half2*)&u.w, *(const __half2*)&v.w);
    add_f32x2(a[0], __half22float2(p0));
    add_f32x2(a[1], __half22float2(p1));
    add_f32x2(a[2], __half22float2(p2));
    add_f32x2(a[3], __half22float2(p3));
}

// tree-of-4: (v0+v1)+(v2+v3) in fp16, then one fp32 accumulate
__device__ __forceinline__ void acc_quad(float2* a, uint4 v0, uint4 v1,
                                         uint4 v2, uint4 v3) {
    __half2 p0 = __hadd2(__hadd2(*(const __half2*)&v0.x, *(const __half2*)&v1.x),
                         __hadd2(*(const __half2*)&v2.x, *(const __half2*)&v3.x));
    __half2 p1 = __hadd2(__hadd2(*(const __half2*)&v0.y, *(const __half2*)&v1.y),
                         __hadd2(*(const __half2*)&v2.y, *(const __half2*)&v3.y));
    __half2 p2 = __hadd2(__hadd2(*(const __half2*)&v0.z, *(const __half2*)&v1.z),
                         __hadd2(*(const __half2*)&v2.z, *(const __half2*)&v3.z));
    __half2 p3 = __hadd2(__hadd2(*(const __half2*)&v0.w, *(const __half2*)&v1.w),
                         __hadd2(*(const __half2*)&v2.w, *(const __half2*)&v3.w));
    add_f32x2(a[0], __half22float2(p0));
    add_f32x2(a[1], __half22float2(p1));
    add_f32x2(a[2], __half22float2(p2));
    add_f32x2(a[3], __half22float2(p3));
}

// tree-of-8 (depth 3) in fp16, then one fp32 accumulate
__device__ __forceinline__ void acc_oct(float2* a, const uint4* v) {
    #pragma unroll
    for (int c = 0; c < 4; c++) {
        const unsigned* w0 = (const unsigned*)&v[0] + c;
        __half2 s01 = __hadd2(*(const __half2*)((const unsigned*)&v[0] + c),
                              *(const __half2*)((const unsigned*)&v[1] + c));
        __half2 s23 = __hadd2(*(const __half2*)((const unsigned*)&v[2] + c),
                              *(const __half2*)((const unsigned*)&v[3] + c));
        __half2 s45 = __hadd2(*(const __half2*)((const unsigned*)&v[4] + c),
                              *(const __half2*)((const unsigned*)&v[5] + c));
        __half2 s67 = __hadd2(*(const __half2*)((const unsigned*)&v[6] + c),
                              *(const __half2*)((const unsigned*)&v[7] + c));
        __half2 p = __hadd2(__hadd2(s01, s23), __hadd2(s45, s67));
        add_f32x2(a[c], __half22float2(p));
        (void)w0;
    }
}

// propagation layer: 8 lanes per dst node ("subwarp"), each lane owns a
// 16B chunk (8 halves) of the 128B row. 4 nodes per warp.
__global__ void __launch_bounds__(256)
prop_kernel(int flip, float* __restrict__ yout) {
    const uint4* __restrict__ zin = (const uint4*)(flip ? g_zB : g_zA);
    uint4* __restrict__ zout      = (uint4*)(flip ? g_zA : g_zB);

    int tid   = blockIdx.x * blockDim.x + threadIdx.x;
    int node  = tid >> 3;         // 8 lanes per node
    int slane = tid & 7;
    if (node >= N_NODES) return;

    int beg = g_rowptr[node];
    int end = g_rowptr[node + 1];

    float2 a[4];
    a[0] = a[1] = a[2] = a[3] = make_float2(0.0f, 0.0f);

    int j = beg;
    for (; j + 8 <= end; j += 8) {
        uint4 v[8];
        #pragma unroll
        for (int k = 0; k < 8; k++) {
            v[k] = zin[g_col[j + k] * 8 + slane];
        }
        acc_oct(a, v);
    }
    if (j + 4 <= end) {
        uint4 v0 = zin[g_col[j + 0] * 8 + slane];
        uint4 v1 = zin[g_col[j + 1] * 8 + slane];
        uint4 v2 = zin[g_col[j + 2] * 8 + slane];
        uint4 v3 = zin[g_col[j + 3] * 8 + slane];
        acc_quad(a, v0, v1, v2, v3);
        j += 4;
    }
    if (j + 2 <= end) {
        uint4 v0 = zin[g_col[j] * 8 + slane];
        uint4 v1 = zin[g_col[j + 1] * 8 + slane];
        acc_pair(a, v0, v1);
        j += 2;
    }
    if (j < end) {
        uint4 v = zin[g_col[j] * 8 + slane];
        acc_chunk(a, v);
    }

    float nd = g_norm[node];
    float s  = ALPHA * nd;
    // last chunk: 8 floats at node*64 + slane*8
    const float4* lp = (const float4*)(g_last + node * C_DIM + slane * 8);
    float4 l0 = lp[0];
    float4 l1 = lp[1];

    float y0 = fminf(fmaxf(fmaf(s, a[0].x, l0.x), 0.0f), 1.0f);
    float y1 = fminf(fmaxf(fmaf(s, a[0].y, l0.y), 0.0f), 1.0f);
    float y2 = fminf(fmaxf(fmaf(s, a[1].x, l0.z), 0.0f), 1.0f);
    float y3 = fminf(fmaxf(fmaf(s, a[1].y, l0.w), 0.0f), 1.0f);
    float y4 = fminf(fmaxf(fmaf(s, a[2].x, l1.x), 0.0f), 1.0f);
    float y5 = fminf(fmaxf(fmaf(s, a[2].y, l1.y), 0.0f), 1.0f);
    float y6 = fminf(fmaxf(fmaf(s, a[3].x, l1.z), 0.0f), 1.0f);
    float y7 = fminf(fmaxf(fmaf(s, a[3].y, l1.w), 0.0f), 1.0f);

    if (yout) {
        float4* op = (float4*)(yout + node * C_DIM + slane * 8);
        op[0] = make_float4(y0, y1, y2, y3);
        op[1] = make_float4(y4, y5, y6, y7);
    } else {
        uint4 o;
        *(__half2*)&o.x = __floats2half2_rn(nd * y0, nd * y1);
        *(__half2*)&o.y = __floats2half2_rn(nd * y2, nd * y3);
        *(__half2*)&o.z = __floats2half2_rn(nd * y4, nd * y5);
        *(__half2*)&o.w = __floats2half2_rn(nd * y6, nd * y7);
        zout[node * 8 + slane] = o;
    }
}

// ------------------------------------------------------------------
extern "C" void kernel_launch(void* const* d_in, const int* in_sizes, int n_in,
                              void* d_out, int out_size) {
    const float* labels   = (const float*)d_in[0];
    const void*  mask_raw = d_in[1];
    const int*   src      = (const int*)d_in[2];
    const int*   dst      = (const int*)d_in[3];
    float*       out      = (float*)d_out;

    const int N = N_NODES;
    const int E = E_EDGES;

    detect_mask_kernel<<<1, 256>>>((const unsigned char*)mask_raw);

    // CSR build
    zero_deg_kernel<<<(N + 255) / 256, 256>>>(N);
    count_deg_kernel<<<(E + 255) / 256, 256>>>(dst, E);
    scan_pass1_kernel<<<NBLK_SCAN, SCAN_TILE>>>(N);
    scan_pass3_kernel<<<NBLK_SCAN, SCAN_TILE>>>(N);   // pass2 folded in
    fill_csr_kernel<<<(E + 255) / 256, 256>>>(src, dst, E);

    // init
    init_kernel<<<(N * C2 + 255) / 256, 256>>>(labels, mask_raw, N);

    // 10 propagation layers (8 threads per node => N*8 threads)
    const int prop_threads = N * 8;
    const int prop_blocks  = (prop_threads + 255) / 256;
    for (int layer = 0; layer < NUM_LAYERS; layer++) {
        int flip = layer & 1;
        float* yo = (layer == NUM_LAYERS - 1) ? out : nullptr;
        prop_kernel<<<prop_blocks, 256>>>(flip, yo);
    }
}

// round 16
// speedup vs baseline: 1.1398x; 1.1398x over previous
#include <cuda_runtime.h>
#include <cuda_fp16.h>
#include <math.h>

#define N_NODES   100000
#define C_DIM     64
#define C2        32          // half2 pairs per row
#define E_EDGES   3200000
#define NUM_LAYERS 10
#define ALPHA     0.9f
#define ONE_M_ALPHA 0.1f
#define SCAN_TILE 1024
#define NBLK_SCAN ((N_NODES + SCAN_TILE - 1) / SCAN_TILE)   // 98

// ---- static device scratch (no allocation allowed) ----
__device__ int     g_deg[N_NODES];
__device__ int     g_rowptr[N_NODES + 1];
__device__ int     g_cursor[N_NODES];
__device__ int     g_col[E_EDGES];
__device__ int     g_part[NBLK_SCAN];
__device__ float   g_norm[N_NODES];
__device__ float   g_last[N_NODES * C_DIM];
__device__ __half2 g_zA[N_NODES * C2];
__device__ __half2 g_zB[N_NODES * C2];
__device__ int     g_mask_is_byte;

// ------------------------------------------------------------------
// zero degree counters; block 0 additionally detects mask element width
__global__ void zero_detect_kernel(const unsigned char* __restrict__ m, int n) {
    int i = blockIdx.x * blockDim.x + threadIdx.x;
    if (i < n) g_deg[i] = 0;
    if (blockIdx.x == 0) {
        __shared__ int any;
        if (threadIdx.x == 0) any = 0;
        __syncthreads();
        for (int k = threadIdx.x; k < 1024; k += blockDim.x)
            if ((k & 3) != 0 && m[k] != 0) atomicOr(&any, 1);
        __syncthreads();
        if (threadIdx.x == 0) g_mask_is_byte = any;
    }
}

__global__ void count_deg_kernel(const int* __restrict__ dst, int e) {
    int i = blockIdx.x * blockDim.x + threadIdx.x;
    if (i < e) {
        int d = dst[i];
        if (d >= 0 && d < N_NODES) atomicAdd(&g_deg[d], 1);
    }
}

__global__ void __launch_bounds__(SCAN_TILE)
scan_pass1_kernel(int n) {
    __shared__ int sh[SCAN_TILE];
    int i = blockIdx.x * SCAN_TILE + threadIdx.x;
    sh[threadIdx.x] = (i < n) ? g_deg[i] : 0;
    __syncthreads();
    #pragma unroll
    for (int off = SCAN_TILE / 2; off > 0; off >>= 1) {
        if (threadIdx.x < off) sh[threadIdx.x] += sh[threadIdx.x + off];
        __syncthreads();
    }
    if (threadIdx.x == 0) g_part[blockIdx.x] = sh[0];
}

// block-local scan; each block also scans the 98 partials itself (replaces pass2)
__global__ void __launch_bounds__(SCAN_TILE)
scan_pass3_kernel(int n) {
    __shared__ int sh[SCAN_TILE];
    __shared__ int shp[128];
    __shared__ int blk_off;
    int t = threadIdx.x;

    if (t < 128) {
        shp[t] = (t < NBLK_SCAN) ? g_part[t] : 0;
    }
    __syncthreads();
    #pragma unroll
    for (int off = 1; off < 128; off <<= 1) {
        int add = 0;
        if (t < 128 && t >= off) add = shp[t - off];
        __syncthreads();
        if (t < 128) shp[t] += add;
        __syncthreads();
    }
    if (t == 0) {
        int b = blockIdx.x;
        int incl = shp[b];
        int own  = (b < NBLK_SCAN) ? g_part[b] : 0;
        blk_off = incl - own;                       // exclusive prefix
        if (b == 0) g_rowptr[n] = shp[127];         // total
    }
    __syncthreads();

    int i = blockIdx.x * SCAN_TILE + t;
    int v = (i < n) ? g_deg[i] : 0;
    sh[t] = v;
    __syncthreads();
    #pragma unroll
    for (int off = 1; off < SCAN_TILE; off <<= 1) {
        int add = (t >= off) ? sh[t - off] : 0;
        __syncthreads();
        sh[t] += add;
        __syncthreads();
    }
    if (i < n) {
        int excl = blk_off + sh[t] - v;
        g_rowptr[i] = excl;
        g_cursor[i] = excl;
        g_norm[i]   = rsqrtf((float)(v > 0 ? v : 1));
    }
}

__global__ void fill_csr_kernel(const int* __restrict__ src,
                                const int* __restrict__ dst, int e) {
    int i = blockIdx.x * blockDim.x + threadIdx.x;
    if (i < e) {
        int d = dst[i];
        int s = src[i];
        if (d >= 0 && d < N_NODES && s >= 0 && s < N_NODES) {
            int p = atomicAdd(&g_cursor[d], 1);
            g_col[p] = s;
        }
    }
}

__global__ void init_kernel(const float* __restrict__ labels,
                            const void* __restrict__ mask_raw, int n) {
    int idx = blockIdx.x * blockDim.x + threadIdx.x;   // over n*C2 pairs
    if (idx >= n * C2) return;
    int node = idx >> 5;
    float2 l = ((const float2*)labels)[idx];
    int mv = g_mask_is_byte ? (int)((const unsigned char*)mask_raw)[node]
                            : ((const int*)mask_raw)[node];
    float m  = mv ? 1.0f : 0.0f;
    float vx = l.x * m, vy = l.y * m;
    ((float2*)g_last)[idx] = make_float2(ONE_M_ALPHA * vx, ONE_M_ALPHA * vy);
    float nn = g_norm[node];
    g_zA[idx] = __floats2half2_rn(nn * vx, nn * vy);
}

// ------------------------------------------------------------------
// packed f32x2 accumulate (Blackwell): one instruction for 2 fp32 adds
__device__ __forceinline__ void add_f32x2(float2& acc, float2 v) {
    unsigned long long a = *(unsigned long long*)&acc;
    unsigned long long b = *(unsigned long long*)&v;
    asm("add.rn.f32x2 %0, %0, %1;" : "+l"(a) : "l"(b));
    *(unsigned long long*)&acc = a;
}

__device__ __forceinline__ void acc_chunk(float2* a, uint4 v) {
    add_f32x2(a[0], __half22float2(*(const __half2*)&v.x));
    add_f32x2(a[1], __half22float2(*(const __half2*)&v.y));
    add_f32x2(a[2], __half22float2(*(const __half2*)&v.z));
    add_f32x2(a[3], __half22float2(*(const __half2*)&v.w));
}

// pair two edges in fp16 (one HADD2 per component), then fp32 accumulate
__device__ __forceinline__ void acc_pair(float2* a, uint4 u, uint4 v) {
    __half2 p0 = __hadd2(*(const __half2*)&u.x, *(const __half2*)&v.x);
    __half2 p1 = __hadd2(*(const __half2*)&u.y, *(const __half2*)&v.y);
    __half2 p2 = __hadd2(*(const __half2*)&u.z, *(const __half2*)&v.z);
    __half2 p3 = __hadd2(*(const __half2*)&u.w, *(const __half2*)&v.w);
    add_f32x2(a[0], __half22float2(p0));
    add_f32x2(a[1], __half22float2(p1));
    add_f32x2(a[2], __half22float2(p2));
    add_f32x2(a[3], __half22float2(p3));
}

// tree-of-4: (v0+v1)+(v2+v3) in fp16, then one fp32 accumulate
__device__ __forceinline__ void acc_quad(float2* a, uint4 v0, uint4 v1,
                                         uint4 v2, uint4 v3) {
    __half2 p0 = __hadd2(__hadd2(*(const __half2*)&v0.x, *(const __half2*)&v1.x),
                         __hadd2(*(const __half2*)&v2.x, *(const __half2*)&v3.x));
    __half2 p1 = __hadd2(__hadd2(*(const __half2*)&v0.y, *(const __half2*)&v1.y),
                         __hadd2(*(const __half2*)&v2.y, *(const __half2*)&v3.y));
    __half2 p2 = __hadd2(__hadd2(*(const __half2*)&v0.z, *(const __half2*)&v1.z),
                         __hadd2(*(const __half2*)&v2.z, *(const __half2*)&v3.z));
    __half2 p3 = __hadd2(__hadd2(*(const __half2*)&v0.w, *(const __half2*)&v1.w),
                         __hadd2(*(const __half2*)&v2.w, *(const __half2*)&v3.w));
    add_f32x2(a[0], __half22float2(p0));
    add_f32x2(a[1], __half22float2(p1));
    add_f32x2(a[2], __half22float2(p2));
    add_f32x2(a[3], __half22float2(p3));
}

// propagation layer: 8 lanes per dst node ("subwarp"), each lane owns a
// 16B chunk (8 halves) of the 128B row. 4 nodes per warp.
__global__ void __launch_bounds__(256)
prop_kernel(int flip, float* __restrict__ yout) {
    const uint4* __restrict__ zin = (const uint4*)(flip ? g_zB : g_zA);
    uint4* __restrict__ zout      = (uint4*)(flip ? g_zA : g_zB);

    int tid   = blockIdx.x * blockDim.x + threadIdx.x;
    int node  = tid >> 3;         // 8 lanes per node
    int slane = tid & 7;
    if (node >= N_NODES) return;

    int beg = g_rowptr[node];
    int end = g_rowptr[node + 1];

    float2 a[4];
    a[0] = a[1] = a[2] = a[3] = make_float2(0.0f, 0.0f);

    int j = beg;
    for (; j + 4 <= end; j += 4) {
        int s0 = g_col[j + 0];
        int s1 = g_col[j + 1];
        int s2 = g_col[j + 2];
        int s3 = g_col[j + 3];
        uint4 v0 = zin[s0 * 8 + slane];
        uint4 v1 = zin[s1 * 8 + slane];
        uint4 v2 = zin[s2 * 8 + slane];
        uint4 v3 = zin[s3 * 8 + slane];
        acc_quad(a, v0, v1, v2, v3);
    }
    if (j + 2 <= end) {
        uint4 v0 = zin[g_col[j] * 8 + slane];
        uint4 v1 = zin[g_col[j + 1] * 8 + slane];
        acc_pair(a, v0, v1);
        j += 2;
    }
    if (j < end) {
        uint4 v = zin[g_col[j] * 8 + slane];
        acc_chunk(a, v);
    }

    float nd = g_norm[node];
    float s  = ALPHA * nd;
    // last chunk: 8 floats at node*64 + slane*8
    const float4* lp = (const float4*)(g_last + node * C_DIM + slane * 8);
    float4 l0 = lp[0];
    float4 l1 = lp[1];

    float y0 = fminf(fmaxf(fmaf(s, a[0].x, l0.x), 0.0f), 1.0f);
    float y1 = fminf(fmaxf(fmaf(s, a[0].y, l0.y), 0.0f), 1.0f);
    float y2 = fminf(fmaxf(fmaf(s, a[1].x, l0.z), 0.0f), 1.0f);
    float y3 = fminf(fmaxf(fmaf(s, a[1].y, l0.w), 0.0f), 1.0f);
    float y4 = fminf(fmaxf(fmaf(s, a[2].x, l1.x), 0.0f), 1.0f);
    float y5 = fminf(fmaxf(fmaf(s, a[2].y, l1.y), 0.0f), 1.0f);
    float y6 = fminf(fmaxf(fmaf(s, a[3].x, l1.z), 0.0f), 1.0f);
    float y7 = fminf(fmaxf(fmaf(s, a[3].y, l1.w), 0.0f), 1.0f);

    if (yout) {
        float4* op = (float4*)(yout + node * C_DIM + slane * 8);
        op[0] = make_float4(y0, y1, y2, y3);
        op[1] = make_float4(y4, y5, y6, y7);
    } else {
        uint4 o;
        *(__half2*)&o.x = __floats2half2_rn(nd * y0, nd * y1);
        *(__half2*)&o.y = __floats2half2_rn(nd * y2, nd * y3);
        *(__half2*)&o.z = __floats2half2_rn(nd * y4, nd * y5);
        *(__half2*)&o.w = __floats2half2_rn(nd * y6, nd * y7);
        zout[node * 8 + slane] = o;
    }
}

// ------------------------------------------------------------------
extern "C" void kernel_launch(void* const* d_in, const int* in_sizes, int n_in,
                              void* d_out, int out_size) {
    const float* labels   = (const float*)d_in[0];
    const void*  mask_raw = d_in[1];
    const int*   src      = (const int*)d_in[2];
    const int*   dst      = (const int*)d_in[3];
    float*       out      = (float*)d_out;

    const int N = N_NODES;
    const int E = E_EDGES;

    // zero degrees + mask width detect (fused)
    zero_detect_kernel<<<(N + 255) / 256, 256>>>((const unsigned char*)mask_raw, N);

    // CSR build
    count_deg_kernel<<<(E + 255) / 256, 256>>>(dst, E);
    scan_pass1_kernel<<<NBLK_SCAN, SCAN_TILE>>>(N);
    scan_pass3_kernel<<<NBLK_SCAN, SCAN_TILE>>>(N);   // pass2 folded in
    fill_csr_kernel<<<(E + 255) / 256, 256>>>(src, dst, E);

    // init
    init_kernel<<<(N * C2 + 255) / 256, 256>>>(labels, mask_raw, N);

    // 10 propagation layers (8 threads per node => N*8 threads)
    const int prop_threads = N * 8;
    const int prop_blocks  = (prop_threads + 255) / 256;
    for (int layer = 0; layer < NUM_LAYERS; layer++) {
        int flip = layer & 1;
        float* yo = (layer == NUM_LAYERS - 1) ? out : nullptr;
        prop_kernel<<<prop_blocks, 256>>>(flip, yo);
    }
}

// round 17
// speedup vs baseline: 1.1476x; 1.0068x over previous
#include <cuda_runtime.h>
#include <cuda_fp16.h>
#include <math.h>

#define N_NODES   100000
#define C_DIM     64
#define C2        32          // half2 pairs per row
#define E_EDGES   3200000
#define NUM_LAYERS 10
#define ALPHA     0.9f
#define ONE_M_ALPHA 0.1f
#define SCAN_TILE 1024
#define NBLK_SCAN ((N_NODES + SCAN_TILE - 1) / SCAN_TILE)   // 98

// ---- static device scratch (no allocation allowed) ----
__device__ int     g_deg[N_NODES];
__device__ int     g_rowptr[N_NODES + 1];
__device__ int     g_cursor[N_NODES];
__device__ int     g_col[E_EDGES];
__device__ int     g_part[NBLK_SCAN];
__device__ float   g_norm[N_NODES];
__device__ float   g_last[N_NODES * C_DIM];
__device__ __half2 g_zA[N_NODES * C2];
__device__ __half2 g_zB[N_NODES * C2];
__device__ int     g_mask_is_byte;

// ------------------------------------------------------------------
// zero degree counters; block 0 additionally detects mask element width
__global__ void zero_detect_kernel(const unsigned char* __restrict__ m, int n) {
    int i = blockIdx.x * blockDim.x + threadIdx.x;
    if (i < n) g_deg[i] = 0;
    if (blockIdx.x == 0) {
        __shared__ int any;
        if (threadIdx.x == 0) any = 0;
        __syncthreads();
        for (int k = threadIdx.x; k < 1024; k += blockDim.x)
            if ((k & 3) != 0 && m[k] != 0) atomicOr(&any, 1);
        __syncthreads();
        if (threadIdx.x == 0) g_mask_is_byte = any;
    }
}

// count in-degrees, 4 edges per thread (int4 loads, independent REDs)
__global__ void count_deg_kernel(const int* __restrict__ dst, int e) {
    int i = blockIdx.x * blockDim.x + threadIdx.x;
    int base = i * 4;
    if (base + 4 <= e) {
        int4 d = *(const int4*)(dst + base);
        atomicAdd(&g_deg[d.x], 1);
        atomicAdd(&g_deg[d.y], 1);
        atomicAdd(&g_deg[d.z], 1);
        atomicAdd(&g_deg[d.w], 1);
    } else {
        for (int k = base; k < e; k++) atomicAdd(&g_deg[dst[k]], 1);
    }
}

__global__ void __launch_bounds__(SCAN_TILE)
scan_pass1_kernel(int n) {
    __shared__ int sh[SCAN_TILE];
    int i = blockIdx.x * SCAN_TILE + threadIdx.x;
    sh[threadIdx.x] = (i < n) ? g_deg[i] : 0;
    __syncthreads();
    #pragma unroll
    for (int off = SCAN_TILE / 2; off > 0; off >>= 1) {
        if (threadIdx.x < off) sh[threadIdx.x] += sh[threadIdx.x + off];
        __syncthreads();
    }
    if (threadIdx.x == 0) g_part[blockIdx.x] = sh[0];
}

// block-local scan; each block also scans the 98 partials itself (replaces pass2)
__global__ void __launch_bounds__(SCAN_TILE)
scan_pass3_kernel(int n) {
    __shared__ int sh[SCAN_TILE];
    __shared__ int shp[128];
    __shared__ int blk_off;
    int t = threadIdx.x;

    if (t < 128) {
        shp[t] = (t < NBLK_SCAN) ? g_part[t] : 0;
    }
    __syncthreads();
    #pragma unroll
    for (int off = 1; off < 128; off <<= 1) {
        int add = 0;
        if (t < 128 && t >= off) add = shp[t - off];
        __syncthreads();
        if (t < 128) shp[t] += add;
        __syncthreads();
    }
    if (t == 0) {
        int b = blockIdx.x;
        int incl = shp[b];
        int own  = (b < NBLK_SCAN) ? g_part[b] : 0;
        blk_off = incl - own;                       // exclusive prefix
        if (b == 0) g_rowptr[n] = shp[127];         // total
    }
    __syncthreads();

    int i = blockIdx.x * SCAN_TILE + t;
    int v = (i < n) ? g_deg[i] : 0;
    sh[t] = v;
    __syncthreads();
    #pragma unroll
    for (int off = 1; off < SCAN_TILE; off <<= 1) {
        int add = (t >= off) ? sh[t - off] : 0;
        __syncthreads();
        sh[t] += add;
        __syncthreads();
    }
    if (i < n) {
        int excl = blk_off + sh[t] - v;
        g_rowptr[i] = excl;
        g_cursor[i] = excl;
        g_norm[i]   = rsqrtf((float)(v > 0 ? v : 1));
    }
}

// fused: blocks [0, fillBlocks) scatter edges into CSR (4 edges/thread);
//        blocks [fillBlocks, ...) init last (fp32) and zA.
__global__ void fill_init_kernel(const int* __restrict__ src,
                                 const int* __restrict__ dst, int e,
                                 const float* __restrict__ labels,
                                 const void* __restrict__ mask_raw, int n,
                                 int fillBlocks) {
    if ((int)blockIdx.x < fillBlocks) {
        int i = blockIdx.x * blockDim.x + threadIdx.x;
        int base = i * 4;
        if (base + 4 <= e) {
            int4 d = *(const int4*)(dst + base);
            int4 s = *(const int4*)(src + base);
            g_col[atomicAdd(&g_cursor[d.x], 1)] = s.x;
            g_col[atomicAdd(&g_cursor[d.y], 1)] = s.y;
            g_col[atomicAdd(&g_cursor[d.z], 1)] = s.z;
            g_col[atomicAdd(&g_cursor[d.w], 1)] = s.w;
        } else {
            for (int k = base; k < e; k++)
                g_col[atomicAdd(&g_cursor[dst[k]], 1)] = src[k];
        }
    } else {
        int idx = (blockIdx.x - fillBlocks) * blockDim.x + threadIdx.x; // n*C2 pairs
        if (idx >= n * C2) return;
        int node = idx >> 5;
        float2 l = ((const float2*)labels)[idx];
        int mv = g_mask_is_byte ? (int)((const unsigned char*)mask_raw)[node]
                                : ((const int*)mask_raw)[node];
        float m  = mv ? 1.0f : 0.0f;
        float vx = l.x * m, vy = l.y * m;
        ((float2*)g_last)[idx] = make_float2(ONE_M_ALPHA * vx, ONE_M_ALPHA * vy);
        float nn = g_norm[node];
        g_zA[idx] = __floats2half2_rn(nn * vx, nn * vy);
    }
}

// ------------------------------------------------------------------
// packed f32x2 accumulate (Blackwell): one instruction for 2 fp32 adds
__device__ __forceinline__ void add_f32x2(float2& acc, float2 v) {
    unsigned long long a = *(unsigned long long*)&acc;
    unsigned long long b = *(unsigned long long*)&v;
    asm("add.rn.f32x2 %0, %0, %1;" : "+l"(a) : "l"(b));
    *(unsigned long long*)&acc = a;
}

__device__ __forceinline__ void acc_chunk(float2* a, uint4 v) {
    add_f32x2(a[0], __half22float2(*(const __half2*)&v.x));
    add_f32x2(a[1], __half22float2(*(const __half2*)&v.y));
    add_f32x2(a[2], __half22float2(*(const __half2*)&v.z));
    add_f32x2(a[3], __half22float2(*(const __half2*)&v.w));
}

// pair two edges in fp16 (one HADD2 per component), then fp32 accumulate
__device__ __forceinline__ void acc_pair(float2* a, uint4 u, uint4 v) {
    __half2 p0 = __hadd2(*(const __half2*)&u.x, *(const __half2*)&v.x);
    __half2 p1 = __hadd2(*(const __half2*)&u.y, *(const __half2*)&v.y);
    __half2 p2 = __hadd2(*(const __half2*)&u.z, *(const __half2*)&v.z);
    __half2 p3 = __hadd2(*(const __half2*)&u.w, *(const __half2*)&v.w);
    add_f32x2(a[0], __half22float2(p0));
    add_f32x2(a[1], __half22float2(p1));
    add_f32x2(a[2], __half22float2(p2));
    add_f32x2(a[3], __half22float2(p3));
}

// tree-of-4: (v0+v1)+(v2+v3) in fp16, then one fp32 accumulate
__device__ __forceinline__ void acc_quad(float2* a, uint4 v0, uint4 v1,
                                         uint4 v2, uint4 v3) {
    __half2 p0 = __hadd2(__hadd2(*(const __half2*)&v0.x, *(const __half2*)&v1.x),
                         __hadd2(*(const __half2*)&v2.x, *(const __half2*)&v3.x));
    __half2 p1 = __hadd2(__hadd2(*(const __half2*)&v0.y, *(const __half2*)&v1.y),
                         __hadd2(*(const __half2*)&v2.y, *(const __half2*)&v3.y));
    __half2 p2 = __hadd2(__hadd2(*(const __half2*)&v0.z, *(const __half2*)&v1.z),
                         __hadd2(*(const __half2*)&v2.z, *(const __half2*)&v3.z));
    __half2 p3 = __hadd2(__hadd2(*(const __half2*)&v0.w, *(const __half2*)&v1.w),
                         __hadd2(*(const __half2*)&v2.w, *(const __half2*)&v3.w));
    add_f32x2(a[0], __half22float2(p0));
    add_f32x2(a[1], __half22float2(p1));
    add_f32x2(a[2], __half22float2(p2));
    add_f32x2(a[3], __half22float2(p3));
}

// propagation layer: 8 lanes per dst node ("subwarp"), each lane owns a
// 16B chunk (8 halves) of the 128B row. 4 nodes per warp.
__global__ void __launch_bounds__(256)
prop_kernel(int flip, float* __restrict__ yout) {
    const uint4* __restrict__ zin = (const uint4*)(flip ? g_zB : g_zA);
    uint4* __restrict__ zout      = (uint4*)(flip ? g_zA : g_zB);

    int tid   = blockIdx.x * blockDim.x + threadIdx.x;
    int node  = tid >> 3;         // 8 lanes per node
    int slane = tid & 7;
    if (node >= N_NODES) return;

    int beg = g_rowptr[node];
    int end = g_rowptr[node + 1];

    float2 a[4];
    a[0] = a[1] = a[2] = a[3] = make_float2(0.0f, 0.0f);

    int j = beg;
    for (; j + 4 <= end; j += 4) {
        int s0 = g_col[j + 0];
        int s1 = g_col[j + 1];
        int s2 = g_col[j + 2];
        int s3 = g_col[j + 3];
        uint4 v0 = zin[s0 * 8 + slane];
        uint4 v1 = zin[s1 * 8 + slane];
        uint4 v2 = zin[s2 * 8 + slane];
        uint4 v3 = zin[s3 * 8 + slane];
        acc_quad(a, v0, v1, v2, v3);
    }
    if (j + 2 <= end) {
        uint4 v0 = zin[g_col[j] * 8 + slane];
        uint4 v1 = zin[g_col[j + 1] * 8 + slane];
        acc_pair(a, v0, v1);
        j += 2;
    }
    if (j < end) {
        uint4 v = zin[g_col[j] * 8 + slane];
        acc_chunk(a, v);
    }

    float nd = g_norm[node];
    float s  = ALPHA * nd;
    // last chunk: 8 floats at node*64 + slane*8
    const float4* lp = (const float4*)(g_last + node * C_DIM + slane * 8);
    float4 l0 = lp[0];
    float4 l1 = lp[1];

    float y0 = fminf(fmaxf(fmaf(s, a[0].x, l0.x), 0.0f), 1.0f);
    float y1 = fminf(fmaxf(fmaf(s, a[0].y, l0.y), 0.0f), 1.0f);
    float y2 = fminf(fmaxf(fmaf(s, a[1].x, l0.z), 0.0f), 1.0f);
    float y3 = fminf(fmaxf(fmaf(s, a[1].y, l0.w), 0.0f), 1.0f);
    float y4 = fminf(fmaxf(fmaf(s, a[2].x, l1.x), 0.0f), 1.0f);
    float y5 = fminf(fmaxf(fmaf(s, a[2].y, l1.y), 0.0f), 1.0f);
    float y6 = fminf(fmaxf(fmaf(s, a[3].x, l1.z), 0.0f), 1.0f);
    float y7 = fminf(fmaxf(fmaf(s, a[3].y, l1.w), 0.0f), 1.0f);

    if (yout) {
        float4* op = (float4*)(yout + node * C_DIM + slane * 8);
        op[0] = make_float4(y0, y1, y2, y3);
        op[1] = make_float4(y4, y5, y6, y7);
    } else {
        uint4 o;
        *(__half2*)&o.x = __floats2half2_rn(nd * y0, nd * y1);
        *(__half2*)&o.y = __floats2half2_rn(nd * y2, nd * y3);
        *(__half2*)&o.z = __floats2half2_rn(nd * y4, nd * y5);
        *(__half2*)&o.w = __floats2half2_rn(nd * y6, nd * y7);
        zout[node * 8 + slane] = o;
    }
}

// ------------------------------------------------------------------
extern "C" void kernel_launch(void* const* d_in, const int* in_sizes, int n_in,
                              void* d_out, int out_size) {
    const float* labels   = (const float*)d_in[0];
    const void*  mask_raw = d_in[1];
    const int*   src      = (const int*)d_in[2];
    const int*   dst      = (const int*)d_in[3];
    float*       out      = (float*)d_out;

    const int N = N_NODES;
    const int E = E_EDGES;

    // zero degrees + mask width detect (fused)
    zero_detect_kernel<<<(N + 255) / 256, 256>>>((const unsigned char*)mask_raw, N);

    // CSR build
    const int quadBlocks = ((E + 3) / 4 + 255) / 256;
    count_deg_kernel<<<quadBlocks, 256>>>(dst, E);
    scan_pass1_kernel<<<NBLK_SCAN, SCAN_TILE>>>(N);
    scan_pass3_kernel<<<NBLK_SCAN, SCAN_TILE>>>(N);   // pass2 folded in

    // fused: CSR scatter (quad) + init (both depend only on pass3)
    const int initBlocks = (N * C2 + 255) / 256;
    fill_init_kernel<<<quadBlocks + initBlocks, 256>>>(src, dst, E, labels,
                                                       mask_raw, N, quadBlocks);

    // 10 propagation layers (8 threads per node => N*8 threads)
    const int prop_threads = N * 8;
    const int prop_blocks  = (prop_threads + 255) / 256;
    for (int layer = 0; layer < NUM_LAYERS; layer++) {
        int flip = layer & 1;
        float* yo = (layer == NUM_LAYERS - 1) ? out : nullptr;
        prop_kernel<<<prop_blocks, 256>>>(flip, yo);
    }
}